// round 11
// baseline (speedup 1.0000x reference)
#include <cuda_runtime.h>
#include <cuda.h>
#include <cuda_fp16.h>
#include <cstdint>

// ============================================================================
// y[b,s,o] = sum_i x[b,s,i]*W[o,i] + bias[o]
//   A = x [M=4096,K=4096] fp32->fp16 ; B = W 3-bit->fp16
// mma.sync.m16n8k16.f16 + TMA + ldmatrix. CTA tile 128x128x64, 3-stage
// pipeline, 8 compute warps (64x32) + 1 producer, 2 CTAs/SM.
// Persistent grid (296), uniform tiles, pipeline carried across tiles.
// R11: next-chunk full-wait hoisted under the k=3 HMMA batch; odd-CTA
// producer staggered ~1us to de-correlate co-resident CTA stalls.
// ============================================================================

static constexpr int M_TOT = 4096;
static constexpr int N_TOT = 4096;
static constexpr int K_TOT = 4096;
static constexpr int GROUPS = (N_TOT * K_TOT) / 32;   // 524288

static constexpr int BM = 128;
static constexpr int BN = 128;
static constexpr int BK = 64;                  // 128 bytes of fp16 per row
static constexpr int STAGES = 3;
static constexpr int NCH = K_TOT / BK;         // 64

static constexpr int GRID = 296;               // 148 SMs x 2 CTAs
static constexpr int NTILES = (M_TOT / BM) * (N_TOT / BN);   // 1024

static constexpr int A_STAGE_BYTES = BM * 128;              // 16 KB
static constexpr int B_STAGE_BYTES = BN * 128;              // 16 KB
static constexpr int STAGE_BYTES = A_STAGE_BYTES + B_STAGE_BYTES;  // 32 KB

static constexpr int SM_FULL  = 0;
static constexpr int SM_EMPTY = SM_FULL + STAGES * 8;
static constexpr int SM_TILE  = 1024;
static constexpr int SMEM_TOTAL = SM_TILE + STAGES * STAGE_BYTES;  // 99328

__device__ __half g_W[(size_t)N_TOT * K_TOT];   // dequantized weights (fp16)
__device__ __half g_X[(size_t)M_TOT * K_TOT];   // fp16 activations

// ===================== PTX helpers =====================

__device__ __forceinline__ uint32_t smem_u32(const void* p) {
    uint32_t a;
    asm("{ .reg .u64 t; cvta.to.shared.u64 t, %1; cvt.u32.u64 %0, t; }"
        : "=r"(a) : "l"(p));
    return a;
}

#define MBARRIER_INIT(addr, cnt) \
    asm volatile("mbarrier.init.shared.b64 [%0], %1;" :: "r"((uint32_t)(addr)), "r"((uint32_t)(cnt)) : "memory")

#define MBARRIER_EXPECT_TX(addr, bytes) \
    asm volatile("mbarrier.arrive.expect_tx.shared.b64 _, [%0], %1;" :: "r"((uint32_t)(addr)), "r"((uint32_t)(bytes)) : "memory")

#define MBARRIER_ARRIVE(addr) \
    asm volatile("mbarrier.arrive.release.cta.shared::cta.b64 _, [%0];" :: "r"((uint32_t)(addr)) : "memory")

#define MBARRIER_WAIT_PARITY_ACQ(mbar_smem_addr, phase_parity) do { \
    uint32_t _mbar = (uint32_t)(mbar_smem_addr); \
    uint32_t _parity = (uint32_t)(phase_parity); \
    uint32_t _done; \
    asm volatile( \
        "{\n\t" \
        ".reg .pred p;\n\t" \
        "mbarrier.try_wait.parity.acquire.cta.shared::cta.b64 p, [%1], %2;\n\t" \
        "selp.b32 %0, 1, 0, p;\n\t" \
        "}" \
        : "=r"(_done) : "r"(_mbar), "r"(_parity) : "memory"); \
    if (!_done) { \
        asm volatile( \
            "{\n\t" \
            ".reg .pred P1;\n\t" \
            "WAIT_LOOP_%=:\n\t" \
            "mbarrier.try_wait.parity.acquire.cta.shared::cta.b64 P1, [%0], %1, 0x989680;\n\t" \
            "@P1 bra.uni WAIT_DONE_%=;\n\t" \
            "bra.uni WAIT_LOOP_%=;\n\t" \
            "WAIT_DONE_%=:\n\t" \
            "}" \
            :: "r"(_mbar), "r"(_parity) : "memory"); \
    } \
} while (0)

#define MBARRIER_WAIT_PARITY_RELAXED(mbar_smem_addr, phase_parity) do { \
    uint32_t _mbar = (uint32_t)(mbar_smem_addr); \
    uint32_t _parity = (uint32_t)(phase_parity); \
    uint32_t _done; \
    asm volatile( \
        "{\n\t" \
        ".reg .pred p;\n\t" \
        "mbarrier.try_wait.parity.relaxed.cta.shared::cta.b64 p, [%1], %2, 0x989680;\n\t" \
        "selp.b32 %0, 1, 0, p;\n\t" \
        "}" \
        : "=r"(_done) : "r"(_mbar), "r"(_parity) : "memory"); \
    if (!_done) { \
        asm volatile( \
            "{\n\t" \
            ".reg .pred P1;\n\t" \
            "WAIT_LOOP_%=:\n\t" \
            "mbarrier.try_wait.parity.relaxed.cta.shared::cta.b64 P1, [%0], %1, 0x989680;\n\t" \
            "@P1 bra.uni WAIT_DONE_%=;\n\t" \
            "bra.uni WAIT_LOOP_%=;\n\t" \
            "WAIT_DONE_%=:\n\t" \
            "}" \
            :: "r"(_mbar), "r"(_parity) : "memory"); \
    } \
} while (0)

#define FENCE_PROXY_ASYNC_SHARED_CTA() \
    asm volatile("fence.proxy.async.shared::cta;" ::: "memory")

#define LDSM_X4(r0, r1, r2, r3, addr) \
    asm volatile("ldmatrix.sync.aligned.m8n8.x4.shared.b16 {%0,%1,%2,%3}, [%4];" \
                 : "=r"(r0), "=r"(r1), "=r"(r2), "=r"(r3) : "r"(addr))

__device__ __forceinline__ void tma2d(uint32_t dst, const CUtensorMap* tm,
                                      int cx, int cy, uint32_t mbar) {
    asm volatile(
        "cp.async.bulk.tensor.2d.shared::cta.global.tile.mbarrier::complete_tx::bytes "
        "[%0], [%1, {%2, %3}], [%4];"
        :: "r"(dst), "l"(tm), "r"(cx), "r"(cy), "r"(mbar) : "memory");
}

__device__ __forceinline__ void mma_f16_16x8x16(
    float& c0, float& c1, float& c2, float& c3,
    uint32_t a0, uint32_t a1, uint32_t a2, uint32_t a3,
    uint32_t b0, uint32_t b1) {
    asm volatile(
        "mma.sync.aligned.m16n8k16.row.col.f32.f16.f16.f32 "
        "{%0,%1,%2,%3}, {%4,%5,%6,%7}, {%8,%9}, {%0,%1,%2,%3};"
        : "+f"(c0), "+f"(c1), "+f"(c2), "+f"(c3)
        : "r"(a0), "r"(a1), "r"(a2), "r"(a3), "r"(b0), "r"(b1));
}

// ===================== Kernel 1: fused prep (dequant W + convert x) ==============
static constexpr int DEQ_BLOCKS = GROUPS / 256;              // 2048
static constexpr int CVT_BLOCKS = (M_TOT * K_TOT / 8) / 256; // 8192

__global__ void prep_kernel(const int* __restrict__ q3,
                            const float* __restrict__ norm,
                            __half* __restrict__ W,
                            const float4* __restrict__ x,
                            uint4* __restrict__ xo) {
    if (blockIdx.x < DEQ_BLOCKS) {
        int g = blockIdx.x * 256 + threadIdx.x;
        const float mv = norm[g];
        const float sc = mv * (2.0f / 7.0f);
        const int4* p4 = reinterpret_cast<const int4*>(q3 + (size_t)g * 12);
        int4 pa = p4[0], pb = p4[1], pc = p4[2];
        int b[12] = {pa.x, pa.y, pa.z, pa.w, pb.x, pb.y, pb.z, pb.w, pc.x, pc.y, pc.z, pc.w};
        __half2 w[16];
#pragma unroll
        for (int t = 0; t < 4; t++) {
            int b0 = b[t * 3], b1 = b[t * 3 + 1], b2 = b[t * 3 + 2];
            int v[8];
            v[0] = b0 & 7;
            v[1] = (b0 >> 3) & 7;
            v[2] = ((b0 >> 6) & 3) | ((b1 & 1) << 2);
            v[3] = (b1 >> 1) & 7;
            v[4] = (b1 >> 4) & 7;
            v[5] = ((b1 >> 7) & 1) | ((b2 & 3) << 1);
            v[6] = (b2 >> 2) & 7;
            v[7] = (b2 >> 5) & 7;
#pragma unroll
            for (int j = 0; j < 4; j++) {
                float f0 = fmaf((float)v[2 * j],     sc, -mv);
                float f1 = fmaf((float)v[2 * j + 1], sc, -mv);
                w[t * 4 + j] = __floats2half2_rn(f0, f1);
            }
        }
        uint4* dst = reinterpret_cast<uint4*>(W + (size_t)g * 32);
        const uint32_t* wu = reinterpret_cast<const uint32_t*>(w);
#pragma unroll
        for (int q = 0; q < 4; q++)
            dst[q] = make_uint4(wu[q * 4], wu[q * 4 + 1], wu[q * 4 + 2], wu[q * 4 + 3]);
    } else {
        int i = (blockIdx.x - DEQ_BLOCKS) * 256 + threadIdx.x;
        float4 v0 = x[2 * i];
        float4 v1 = x[2 * i + 1];
        __half2 h0 = __floats2half2_rn(v0.x, v0.y);
        __half2 h1 = __floats2half2_rn(v0.z, v0.w);
        __half2 h2 = __floats2half2_rn(v1.x, v1.y);
        __half2 h3 = __floats2half2_rn(v1.z, v1.w);
        xo[i] = make_uint4(*reinterpret_cast<uint32_t*>(&h0), *reinterpret_cast<uint32_t*>(&h1),
                           *reinterpret_cast<uint32_t*>(&h2), *reinterpret_cast<uint32_t*>(&h3));
    }
}

// ===================== Kernel 2: persistent mma.sync fp16 GEMM =====================
// 288 threads: warps 0..7 compute 64x32 warp tiles, warp 8 = TMA producer.
// Grid 296 persistent CTAs; uniform 128x128 full-K tiles; pipeline state
// carried across tiles; next-chunk wait hoisted under k=3 HMMAs.

__global__ void __launch_bounds__(288, 2)
gemm_f16_kernel(const float* __restrict__ bias, float* __restrict__ out,
                const __grid_constant__ CUtensorMap tmA,
                const __grid_constant__ CUtensorMap tmB) {
    extern __shared__ char smem[];
    const uint32_t sb = smem_u32(smem);
    const int tid = threadIdx.x;
    const int wid = tid >> 5;
    const int lid = tid & 31;

    if (tid == 0) {
        for (int s = 0; s < STAGES; s++) {
            MBARRIER_INIT(sb + SM_FULL + s * 8, 1);
            MBARRIER_INIT(sb + SM_EMPTY + s * 8, 8);
        }
        FENCE_PROXY_ASYNC_SHARED_CTA();
    }
    __syncthreads();

    if (wid == 8) {
        // ---------------- TMA producer warp (persistent, no drain) ----------------
        if (lid == 0) {
            // de-correlate the two co-resident CTAs' stage boundaries
            if (blockIdx.x & 1) __nanosleep(1000);
            int s = 0, ph = 1;
            for (int u = blockIdx.x; u < NTILES; u += GRID) {
                const int m0 = (u & 31) * BM;
                const int n0 = (u >> 5) * BN;
                for (int j = 0; j < NCH; j++) {
                    MBARRIER_WAIT_PARITY_RELAXED(sb + SM_EMPTY + s * 8, ph);
                    MBARRIER_EXPECT_TX(sb + SM_FULL + s * 8, STAGE_BYTES);
                    uint32_t dstA = sb + SM_TILE + s * STAGE_BYTES;
                    tma2d(dstA, &tmA, j * BK, m0, sb + SM_FULL + s * 8);
                    tma2d(dstA + A_STAGE_BYTES, &tmB, j * BK, n0, sb + SM_FULL + s * 8);
                    if (++s == STAGES) { s = 0; ph ^= 1; }
                }
            }
        }
        return;
    }

    // ---------------- compute warps ----------------
    const int warp_m = wid & 1;       // 64 rows
    const int warp_n = wid >> 1;      // 32 cols
    const int lr4 = lid >> 2;
    const int lc4 = lid & 3;
    const int mi = lid >> 3;
    const int r  = lid & 7;

    uint32_t aRow[4];
#pragma unroll
    for (int m = 0; m < 4; m++)
        aRow[m] = (uint32_t)(warp_m * 64 + m * 16 + (mi & 1) * 8 + r) * 128u;
    uint32_t cA[4];
#pragma unroll
    for (int k = 0; k < 4; k++)
        cA[k] = 16u * (uint32_t)((2 * k + (mi >> 1)) ^ r);

    uint32_t bRow[2];
#pragma unroll
    for (int t = 0; t < 2; t++)
        bRow[t] = (uint32_t)(warp_n * 32 + t * 16 + (mi >> 1) * 8 + r) * 128u;
    uint32_t cB[4];
#pragma unroll
    for (int k = 0; k < 4; k++)
        cB[k] = 16u * (uint32_t)((2 * k + (mi & 1)) ^ r);

    int s = 0, ph = 0;
    // wait for the very first stage up front; afterwards every wait is
    // hoisted under the previous chunk's k=3 HMMA batch.
    MBARRIER_WAIT_PARITY_ACQ(sb + SM_FULL + 0, 0);

    for (int u = blockIdx.x; u < NTILES; u += GRID) {
        const int m0 = (u & 31) * BM;
        const int n0 = (u >> 5) * BN;
        const bool last_tile = (u + GRID >= NTILES);

        float acc[4][4][4];
#pragma unroll
        for (int m = 0; m < 4; m++)
#pragma unroll
            for (int n = 0; n < 4; n++)
#pragma unroll
                for (int q = 0; q < 4; q++) acc[m][n][q] = 0.0f;

        for (int j = 0; j < NCH; j++) {
            // stage s is known-full here (waited at end of previous chunk)
            const uint32_t pa = sb + SM_TILE + s * STAGE_BYTES;
            const uint32_t pb = pa + A_STAGE_BYTES;
            const bool last_chunk = last_tile && (j == NCH - 1);

#pragma unroll
            for (int k = 0; k < 4; k++) {
                uint32_t af[4][4];
#pragma unroll
                for (int m = 0; m < 4; m++)
                    LDSM_X4(af[m][0], af[m][1], af[m][2], af[m][3], pa + aRow[m] + cA[k]);
                uint32_t bf[4][2];
#pragma unroll
                for (int t = 0; t < 2; t++)
                    LDSM_X4(bf[2 * t][0], bf[2 * t][1], bf[2 * t + 1][0], bf[2 * t + 1][1],
                            pb + bRow[t] + cB[k]);
                if (k == 3) {
                    // all of this warp's smem reads for the stage are issued:
                    // release the stage, advance, and pre-wait the next stage
                    // while the k=0..2 HMMAs drain the tensor pipe.
                    if (lid == 0) MBARRIER_ARRIVE(sb + SM_EMPTY + s * 8);
                    if (++s == STAGES) { s = 0; ph ^= 1; }
                    if (!last_chunk) {
                        MBARRIER_WAIT_PARITY_ACQ(sb + SM_FULL + s * 8, ph);
                    }
                }
#pragma unroll
                for (int m = 0; m < 4; m++)
#pragma unroll
                    for (int n = 0; n < 4; n++)
                        mma_f16_16x8x16(acc[m][n][0], acc[m][n][1], acc[m][n][2], acc[m][n][3],
                                        af[m][0], af[m][1], af[m][2], af[m][3],
                                        bf[n][0], bf[n][1]);
            }
        }

        // ---------------- epilogue (overlapped with producer prefetch) --------
        const int orow0 = m0 + warp_m * 64 + lr4;
        const int ocol0 = n0 + warp_n * 32 + 2 * lc4;
#pragma unroll
        for (int m = 0; m < 4; m++) {
#pragma unroll
            for (int n = 0; n < 4; n++) {
                const int col = ocol0 + n * 8;
                const float2 bv = *reinterpret_cast<const float2*>(bias + col);
                float* p0 = out + (size_t)(orow0 + m * 16) * N_TOT + col;
                float* p1 = out + (size_t)(orow0 + m * 16 + 8) * N_TOT + col;
                *reinterpret_cast<float2*>(p0) =
                    make_float2(acc[m][n][0] + bv.x, acc[m][n][1] + bv.y);
                *reinterpret_cast<float2*>(p1) =
                    make_float2(acc[m][n][2] + bv.x, acc[m][n][3] + bv.y);
            }
        }
    }
}

// ===================== Host =====================

typedef CUresult (*cuTensorMapEncodeTiled_t)(
    CUtensorMap*, CUtensorMapDataType, cuuint32_t, void*,
    const cuuint64_t*, const cuuint64_t*, const cuuint32_t*, const cuuint32_t*,
    CUtensorMapInterleave, CUtensorMapSwizzle, CUtensorMapL2promotion,
    CUtensorMapFloatOOBfill);

static void make_desc(cuTensorMapEncodeTiled_t enc, CUtensorMap* tm,
                      const void* base, uint32_t box_rows) {
    cuuint64_t dims[2] = {(cuuint64_t)K_TOT, (cuuint64_t)4096};
    cuuint64_t strides[1] = {(cuuint64_t)K_TOT * sizeof(__half)};
    cuuint32_t box[2] = {(cuuint32_t)BK, box_rows};
    cuuint32_t estr[2] = {1, 1};
    enc(tm, CU_TENSOR_MAP_DATA_TYPE_UINT16, 2, const_cast<void*>(base),
        dims, strides, box, estr,
        CU_TENSOR_MAP_INTERLEAVE_NONE, CU_TENSOR_MAP_SWIZZLE_128B,
        CU_TENSOR_MAP_L2_PROMOTION_L2_128B, CU_TENSOR_MAP_FLOAT_OOB_FILL_NONE);
}

extern "C" void kernel_launch(void* const* d_in, const int* in_sizes, int n_in,
                              void* d_out, int out_size) {
    const float* x    = (const float*)d_in[0];
    const int*   q3   = (const int*)d_in[1];
    const float* norm = (const float*)d_in[2];
    const float* bias = (const float*)d_in[3];
    float* out = (float*)d_out;

    void* wptr = nullptr;
    cudaGetSymbolAddress(&wptr, g_W);
    void* xptr = nullptr;
    cudaGetSymbolAddress(&xptr, g_X);

    void* fn = nullptr;
    cudaDriverEntryPointQueryResult qr;
    cudaGetDriverEntryPointByVersion("cuTensorMapEncodeTiled", &fn, 12000,
                                     cudaEnableDefault, &qr);
    cuTensorMapEncodeTiled_t enc = (cuTensorMapEncodeTiled_t)fn;

    CUtensorMap tmA, tmB;
    make_desc(enc, &tmA, xptr, (uint32_t)BM);
    make_desc(enc, &tmB, wptr, (uint32_t)BN);

    prep_kernel<<<DEQ_BLOCKS + CVT_BLOCKS, 256>>>(
        q3, norm, (__half*)wptr, (const float4*)x, (uint4*)xptr);

    cudaFuncSetAttribute(gemm_f16_kernel,
                         cudaFuncAttributeMaxDynamicSharedMemorySize, SMEM_TOTAL);
    gemm_f16_kernel<<<GRID, 288, SMEM_TOTAL>>>(bias, out, tmA, tmB);
}

// round 12
// speedup vs baseline: 1.7474x; 1.7474x over previous
#include <cuda_runtime.h>
#include <cuda.h>
#include <cuda_fp16.h>
#include <cstdint>

// ============================================================================
// y[b,s,o] = sum_i x[b,s,i]*W[o,i] + bias[o]
//   A = x [M=4096,K=4096] fp32->fp16 ; B = W 3-bit->fp16
// mma.sync.m16n8k16.f16 + TMA + ldmatrix. CTA tile 128x128x64, 3-stage
// pipeline, 8 compute warps (64x32) + 1 producer, 2 CTAs/SM.
// Persistent grid (296), uniform tiles, pipeline carried across tiles.
// R12 = R10 hot path VERBATIM (the R11 wait-hoist regressed 313->551 by
// breaking ptxas's LDSM/HMMA schedule) + isolated odd-CTA producer stagger.
// ============================================================================

static constexpr int M_TOT = 4096;
static constexpr int N_TOT = 4096;
static constexpr int K_TOT = 4096;
static constexpr int GROUPS = (N_TOT * K_TOT) / 32;   // 524288

static constexpr int BM = 128;
static constexpr int BN = 128;
static constexpr int BK = 64;                  // 128 bytes of fp16 per row
static constexpr int STAGES = 3;
static constexpr int NCH = K_TOT / BK;         // 64

static constexpr int GRID = 296;               // 148 SMs x 2 CTAs
static constexpr int NTILES = (M_TOT / BM) * (N_TOT / BN);   // 1024

static constexpr int A_STAGE_BYTES = BM * 128;              // 16 KB
static constexpr int B_STAGE_BYTES = BN * 128;              // 16 KB
static constexpr int STAGE_BYTES = A_STAGE_BYTES + B_STAGE_BYTES;  // 32 KB

static constexpr int SM_FULL  = 0;
static constexpr int SM_EMPTY = SM_FULL + STAGES * 8;
static constexpr int SM_TILE  = 1024;
static constexpr int SMEM_TOTAL = SM_TILE + STAGES * STAGE_BYTES;  // 99328

__device__ __half g_W[(size_t)N_TOT * K_TOT];   // dequantized weights (fp16)
__device__ __half g_X[(size_t)M_TOT * K_TOT];   // fp16 activations

// ===================== PTX helpers =====================

__device__ __forceinline__ uint32_t smem_u32(const void* p) {
    uint32_t a;
    asm("{ .reg .u64 t; cvta.to.shared.u64 t, %1; cvt.u32.u64 %0, t; }"
        : "=r"(a) : "l"(p));
    return a;
}

#define MBARRIER_INIT(addr, cnt) \
    asm volatile("mbarrier.init.shared.b64 [%0], %1;" :: "r"((uint32_t)(addr)), "r"((uint32_t)(cnt)) : "memory")

#define MBARRIER_EXPECT_TX(addr, bytes) \
    asm volatile("mbarrier.arrive.expect_tx.shared.b64 _, [%0], %1;" :: "r"((uint32_t)(addr)), "r"((uint32_t)(bytes)) : "memory")

#define MBARRIER_ARRIVE(addr) \
    asm volatile("mbarrier.arrive.release.cta.shared::cta.b64 _, [%0];" :: "r"((uint32_t)(addr)) : "memory")

#define MBARRIER_WAIT_PARITY_ACQ(mbar_smem_addr, phase_parity) do { \
    uint32_t _mbar = (uint32_t)(mbar_smem_addr); \
    uint32_t _parity = (uint32_t)(phase_parity); \
    uint32_t _done; \
    asm volatile( \
        "{\n\t" \
        ".reg .pred p;\n\t" \
        "mbarrier.try_wait.parity.acquire.cta.shared::cta.b64 p, [%1], %2;\n\t" \
        "selp.b32 %0, 1, 0, p;\n\t" \
        "}" \
        : "=r"(_done) : "r"(_mbar), "r"(_parity) : "memory"); \
    if (!_done) { \
        asm volatile( \
            "{\n\t" \
            ".reg .pred P1;\n\t" \
            "WAIT_LOOP_%=:\n\t" \
            "mbarrier.try_wait.parity.acquire.cta.shared::cta.b64 P1, [%0], %1, 0x989680;\n\t" \
            "@P1 bra.uni WAIT_DONE_%=;\n\t" \
            "bra.uni WAIT_LOOP_%=;\n\t" \
            "WAIT_DONE_%=:\n\t" \
            "}" \
            :: "r"(_mbar), "r"(_parity) : "memory"); \
    } \
} while (0)

#define MBARRIER_WAIT_PARITY_RELAXED(mbar_smem_addr, phase_parity) do { \
    uint32_t _mbar = (uint32_t)(mbar_smem_addr); \
    uint32_t _parity = (uint32_t)(phase_parity); \
    uint32_t _done; \
    asm volatile( \
        "{\n\t" \
        ".reg .pred p;\n\t" \
        "mbarrier.try_wait.parity.relaxed.cta.shared::cta.b64 p, [%1], %2, 0x989680;\n\t" \
        "selp.b32 %0, 1, 0, p;\n\t" \
        "}" \
        : "=r"(_done) : "r"(_mbar), "r"(_parity) : "memory"); \
    if (!_done) { \
        asm volatile( \
            "{\n\t" \
            ".reg .pred P1;\n\t" \
            "WAIT_LOOP_%=:\n\t" \
            "mbarrier.try_wait.parity.relaxed.cta.shared::cta.b64 P1, [%0], %1, 0x989680;\n\t" \
            "@P1 bra.uni WAIT_DONE_%=;\n\t" \
            "bra.uni WAIT_LOOP_%=;\n\t" \
            "WAIT_DONE_%=:\n\t" \
            "}" \
            :: "r"(_mbar), "r"(_parity) : "memory"); \
    } \
} while (0)

#define FENCE_PROXY_ASYNC_SHARED_CTA() \
    asm volatile("fence.proxy.async.shared::cta;" ::: "memory")

#define LDSM_X4(r0, r1, r2, r3, addr) \
    asm volatile("ldmatrix.sync.aligned.m8n8.x4.shared.b16 {%0,%1,%2,%3}, [%4];" \
                 : "=r"(r0), "=r"(r1), "=r"(r2), "=r"(r3) : "r"(addr))

__device__ __forceinline__ void tma2d(uint32_t dst, const CUtensorMap* tm,
                                      int cx, int cy, uint32_t mbar) {
    asm volatile(
        "cp.async.bulk.tensor.2d.shared::cta.global.tile.mbarrier::complete_tx::bytes "
        "[%0], [%1, {%2, %3}], [%4];"
        :: "r"(dst), "l"(tm), "r"(cx), "r"(cy), "r"(mbar) : "memory");
}

__device__ __forceinline__ void mma_f16_16x8x16(
    float& c0, float& c1, float& c2, float& c3,
    uint32_t a0, uint32_t a1, uint32_t a2, uint32_t a3,
    uint32_t b0, uint32_t b1) {
    asm volatile(
        "mma.sync.aligned.m16n8k16.row.col.f32.f16.f16.f32 "
        "{%0,%1,%2,%3}, {%4,%5,%6,%7}, {%8,%9}, {%0,%1,%2,%3};"
        : "+f"(c0), "+f"(c1), "+f"(c2), "+f"(c3)
        : "r"(a0), "r"(a1), "r"(a2), "r"(a3), "r"(b0), "r"(b1));
}

// ===================== Kernel 1: fused prep (dequant W + convert x) ==============
static constexpr int DEQ_BLOCKS = GROUPS / 256;              // 2048
static constexpr int CVT_BLOCKS = (M_TOT * K_TOT / 8) / 256; // 8192

__global__ void prep_kernel(const int* __restrict__ q3,
                            const float* __restrict__ norm,
                            __half* __restrict__ W,
                            const float4* __restrict__ x,
                            uint4* __restrict__ xo) {
    if (blockIdx.x < DEQ_BLOCKS) {
        int g = blockIdx.x * 256 + threadIdx.x;
        const float mv = norm[g];
        const float sc = mv * (2.0f / 7.0f);
        const int4* p4 = reinterpret_cast<const int4*>(q3 + (size_t)g * 12);
        int4 pa = p4[0], pb = p4[1], pc = p4[2];
        int b[12] = {pa.x, pa.y, pa.z, pa.w, pb.x, pb.y, pb.z, pb.w, pc.x, pc.y, pc.z, pc.w};
        __half2 w[16];
#pragma unroll
        for (int t = 0; t < 4; t++) {
            int b0 = b[t * 3], b1 = b[t * 3 + 1], b2 = b[t * 3 + 2];
            int v[8];
            v[0] = b0 & 7;
            v[1] = (b0 >> 3) & 7;
            v[2] = ((b0 >> 6) & 3) | ((b1 & 1) << 2);
            v[3] = (b1 >> 1) & 7;
            v[4] = (b1 >> 4) & 7;
            v[5] = ((b1 >> 7) & 1) | ((b2 & 3) << 1);
            v[6] = (b2 >> 2) & 7;
            v[7] = (b2 >> 5) & 7;
#pragma unroll
            for (int j = 0; j < 4; j++) {
                float f0 = fmaf((float)v[2 * j],     sc, -mv);
                float f1 = fmaf((float)v[2 * j + 1], sc, -mv);
                w[t * 4 + j] = __floats2half2_rn(f0, f1);
            }
        }
        uint4* dst = reinterpret_cast<uint4*>(W + (size_t)g * 32);
        const uint32_t* wu = reinterpret_cast<const uint32_t*>(w);
#pragma unroll
        for (int q = 0; q < 4; q++)
            dst[q] = make_uint4(wu[q * 4], wu[q * 4 + 1], wu[q * 4 + 2], wu[q * 4 + 3]);
    } else {
        int i = (blockIdx.x - DEQ_BLOCKS) * 256 + threadIdx.x;
        float4 v0 = x[2 * i];
        float4 v1 = x[2 * i + 1];
        __half2 h0 = __floats2half2_rn(v0.x, v0.y);
        __half2 h1 = __floats2half2_rn(v0.z, v0.w);
        __half2 h2 = __floats2half2_rn(v1.x, v1.y);
        __half2 h3 = __floats2half2_rn(v1.z, v1.w);
        xo[i] = make_uint4(*reinterpret_cast<uint32_t*>(&h0), *reinterpret_cast<uint32_t*>(&h1),
                           *reinterpret_cast<uint32_t*>(&h2), *reinterpret_cast<uint32_t*>(&h3));
    }
}

// ===================== Kernel 2: persistent mma.sync fp16 GEMM =====================
// 288 threads: warps 0..7 compute 64x32 warp tiles, warp 8 = TMA producer.
// Grid 296 persistent CTAs; all tiles uniform 128x128 full-K; pipeline state
// (stage index s, phase ph) carried across tile boundaries on both sides.
// Hot path identical to the 313.9us R10 kernel.

__global__ void __launch_bounds__(288, 2)
gemm_f16_kernel(const float* __restrict__ bias, float* __restrict__ out,
                const __grid_constant__ CUtensorMap tmA,
                const __grid_constant__ CUtensorMap tmB) {
    extern __shared__ char smem[];
    const uint32_t sb = smem_u32(smem);
    const int tid = threadIdx.x;
    const int wid = tid >> 5;
    const int lid = tid & 31;

    if (tid == 0) {
        for (int s = 0; s < STAGES; s++) {
            MBARRIER_INIT(sb + SM_FULL + s * 8, 1);
            MBARRIER_INIT(sb + SM_EMPTY + s * 8, 8);
        }
        FENCE_PROXY_ASYNC_SHARED_CTA();
    }
    __syncthreads();

    if (wid == 8) {
        // ---------------- TMA producer warp (persistent, no drain) ----------------
        if (lid == 0) {
            // isolated change vs R10: de-correlate the two co-resident CTAs'
            // stage boundaries with a one-time ~1us stagger.
            if (blockIdx.x & 1) __nanosleep(1000);
            int s = 0, ph = 1;
            for (int u = blockIdx.x; u < NTILES; u += GRID) {
                const int m0 = (u & 31) * BM;
                const int n0 = (u >> 5) * BN;
                for (int j = 0; j < NCH; j++) {
                    MBARRIER_WAIT_PARITY_RELAXED(sb + SM_EMPTY + s * 8, ph);
                    MBARRIER_EXPECT_TX(sb + SM_FULL + s * 8, STAGE_BYTES);
                    uint32_t dstA = sb + SM_TILE + s * STAGE_BYTES;
                    tma2d(dstA, &tmA, j * BK, m0, sb + SM_FULL + s * 8);
                    tma2d(dstA + A_STAGE_BYTES, &tmB, j * BK, n0, sb + SM_FULL + s * 8);
                    if (++s == STAGES) { s = 0; ph ^= 1; }
                }
            }
        }
        return;
    }

    // ---------------- compute warps ----------------
    const int warp_m = wid & 1;       // 64 rows
    const int warp_n = wid >> 1;      // 32 cols
    const int lr4 = lid >> 2;
    const int lc4 = lid & 3;
    const int mi = lid >> 3;
    const int r  = lid & 7;

    uint32_t aRow[4];
#pragma unroll
    for (int m = 0; m < 4; m++)
        aRow[m] = (uint32_t)(warp_m * 64 + m * 16 + (mi & 1) * 8 + r) * 128u;
    uint32_t cA[4];
#pragma unroll
    for (int k = 0; k < 4; k++)
        cA[k] = 16u * (uint32_t)((2 * k + (mi >> 1)) ^ r);

    uint32_t bRow[2];
#pragma unroll
    for (int t = 0; t < 2; t++)
        bRow[t] = (uint32_t)(warp_n * 32 + t * 16 + (mi >> 1) * 8 + r) * 128u;
    uint32_t cB[4];
#pragma unroll
    for (int k = 0; k < 4; k++)
        cB[k] = 16u * (uint32_t)((2 * k + (mi & 1)) ^ r);

    int s = 0, ph = 0;
    for (int u = blockIdx.x; u < NTILES; u += GRID) {
        const int m0 = (u & 31) * BM;
        const int n0 = (u >> 5) * BN;

        float acc[4][4][4];
#pragma unroll
        for (int m = 0; m < 4; m++)
#pragma unroll
            for (int n = 0; n < 4; n++)
#pragma unroll
                for (int q = 0; q < 4; q++) acc[m][n][q] = 0.0f;

        for (int j = 0; j < NCH; j++) {
            MBARRIER_WAIT_PARITY_ACQ(sb + SM_FULL + s * 8, ph);
            const uint32_t pa = sb + SM_TILE + s * STAGE_BYTES;
            const uint32_t pb = pa + A_STAGE_BYTES;

#pragma unroll
            for (int k = 0; k < 4; k++) {
                uint32_t af[4][4];
#pragma unroll
                for (int m = 0; m < 4; m++)
                    LDSM_X4(af[m][0], af[m][1], af[m][2], af[m][3], pa + aRow[m] + cA[k]);
                uint32_t bf[4][2];
#pragma unroll
                for (int t = 0; t < 2; t++)
                    LDSM_X4(bf[2 * t][0], bf[2 * t][1], bf[2 * t + 1][0], bf[2 * t + 1][1],
                            pb + bRow[t] + cB[k]);
                // after the LAST k-step's LDSMs are issued, this warp's smem
                // reads for the stage are in flight -> release the stage early
                // (HMMAs below touch only registers).
                if (k == 3 && lid == 0) MBARRIER_ARRIVE(sb + SM_EMPTY + s * 8);
#pragma unroll
                for (int m = 0; m < 4; m++)
#pragma unroll
                    for (int n = 0; n < 4; n++)
                        mma_f16_16x8x16(acc[m][n][0], acc[m][n][1], acc[m][n][2], acc[m][n][3],
                                        af[m][0], af[m][1], af[m][2], af[m][3],
                                        bf[n][0], bf[n][1]);
            }
            if (++s == STAGES) { s = 0; ph ^= 1; }
        }

        // ---------------- epilogue (overlapped with producer prefetch) --------
        const int orow0 = m0 + warp_m * 64 + lr4;
        const int ocol0 = n0 + warp_n * 32 + 2 * lc4;
#pragma unroll
        for (int m = 0; m < 4; m++) {
#pragma unroll
            for (int n = 0; n < 4; n++) {
                const int col = ocol0 + n * 8;
                const float2 bv = *reinterpret_cast<const float2*>(bias + col);
                float* p0 = out + (size_t)(orow0 + m * 16) * N_TOT + col;
                float* p1 = out + (size_t)(orow0 + m * 16 + 8) * N_TOT + col;
                *reinterpret_cast<float2*>(p0) =
                    make_float2(acc[m][n][0] + bv.x, acc[m][n][1] + bv.y);
                *reinterpret_cast<float2*>(p1) =
                    make_float2(acc[m][n][2] + bv.x, acc[m][n][3] + bv.y);
            }
        }
    }
}

// ===================== Host =====================

typedef CUresult (*cuTensorMapEncodeTiled_t)(
    CUtensorMap*, CUtensorMapDataType, cuuint32_t, void*,
    const cuuint64_t*, const cuuint64_t*, const cuuint32_t*, const cuuint32_t*,
    CUtensorMapInterleave, CUtensorMapSwizzle, CUtensorMapL2promotion,
    CUtensorMapFloatOOBfill);

static void make_desc(cuTensorMapEncodeTiled_t enc, CUtensorMap* tm,
                      const void* base, uint32_t box_rows) {
    cuuint64_t dims[2] = {(cuuint64_t)K_TOT, (cuuint64_t)4096};
    cuuint64_t strides[1] = {(cuuint64_t)K_TOT * sizeof(__half)};
    cuuint32_t box[2] = {(cuuint32_t)BK, box_rows};
    cuuint32_t estr[2] = {1, 1};
    enc(tm, CU_TENSOR_MAP_DATA_TYPE_UINT16, 2, const_cast<void*>(base),
        dims, strides, box, estr,
        CU_TENSOR_MAP_INTERLEAVE_NONE, CU_TENSOR_MAP_SWIZZLE_128B,
        CU_TENSOR_MAP_L2_PROMOTION_L2_128B, CU_TENSOR_MAP_FLOAT_OOB_FILL_NONE);
}

extern "C" void kernel_launch(void* const* d_in, const int* in_sizes, int n_in,
                              void* d_out, int out_size) {
    const float* x    = (const float*)d_in[0];
    const int*   q3   = (const int*)d_in[1];
    const float* norm = (const float*)d_in[2];
    const float* bias = (const float*)d_in[3];
    float* out = (float*)d_out;

    void* wptr = nullptr;
    cudaGetSymbolAddress(&wptr, g_W);
    void* xptr = nullptr;
    cudaGetSymbolAddress(&xptr, g_X);

    void* fn = nullptr;
    cudaDriverEntryPointQueryResult qr;
    cudaGetDriverEntryPointByVersion("cuTensorMapEncodeTiled", &fn, 12000,
                                     cudaEnableDefault, &qr);
    cuTensorMapEncodeTiled_t enc = (cuTensorMapEncodeTiled_t)fn;

    CUtensorMap tmA, tmB;
    make_desc(enc, &tmA, xptr, (uint32_t)BM);
    make_desc(enc, &tmB, wptr, (uint32_t)BN);

    prep_kernel<<<DEQ_BLOCKS + CVT_BLOCKS, 256>>>(
        q3, norm, (__half*)wptr, (const float4*)x, (uint4*)xptr);

    cudaFuncSetAttribute(gemm_f16_kernel,
                         cudaFuncAttributeMaxDynamicSharedMemorySize, SMEM_TOTAL);
    gemm_f16_kernel<<<GRID, 288, SMEM_TOTAL>>>(bias, out, tmA, tmB);
}

// round 13
// speedup vs baseline: 1.7567x; 1.0053x over previous
#include <cuda_runtime.h>
#include <cuda.h>
#include <cuda_fp16.h>
#include <cstdint>

// ============================================================================
// y[b,s,o] = sum_i x[b,s,i]*W[o,i] + bias[o]
//   A = x [M=4096,K=4096] fp32->fp16 ; B = W 3-bit->fp16
// mma.sync.m16n8k16.f16 + TMA + ldmatrix. CTA tile 128x128x64, 3-stage
// pipeline, 8 compute warps (64x32) + 1 producer, 2 CTAs/SM.
// Persistent grid (296), uniform tiles, pipeline carried across tiles.
// R13: SAFE stage release — empty-barrier arrive AFTER the k-loop, where the
// k=3 HMMAs' scoreboard waits guarantee all LDSM smem reads completed.
// (R10/R12 arrived between LDSM issue and HMMA issue: latent use-after-free
// race vs the producer's TMA, exposed by R12's timing stagger as a rel_err
// shift on byte-identical arithmetic.)
// ============================================================================

static constexpr int M_TOT = 4096;
static constexpr int N_TOT = 4096;
static constexpr int K_TOT = 4096;
static constexpr int GROUPS = (N_TOT * K_TOT) / 32;   // 524288

static constexpr int BM = 128;
static constexpr int BN = 128;
static constexpr int BK = 64;                  // 128 bytes of fp16 per row
static constexpr int STAGES = 3;
static constexpr int NCH = K_TOT / BK;         // 64

static constexpr int GRID = 296;               // 148 SMs x 2 CTAs
static constexpr int NTILES = (M_TOT / BM) * (N_TOT / BN);   // 1024

static constexpr int A_STAGE_BYTES = BM * 128;              // 16 KB
static constexpr int B_STAGE_BYTES = BN * 128;              // 16 KB
static constexpr int STAGE_BYTES = A_STAGE_BYTES + B_STAGE_BYTES;  // 32 KB

static constexpr int SM_FULL  = 0;
static constexpr int SM_EMPTY = SM_FULL + STAGES * 8;
static constexpr int SM_TILE  = 1024;
static constexpr int SMEM_TOTAL = SM_TILE + STAGES * STAGE_BYTES;  // 99328

__device__ __half g_W[(size_t)N_TOT * K_TOT];   // dequantized weights (fp16)
__device__ __half g_X[(size_t)M_TOT * K_TOT];   // fp16 activations

// ===================== PTX helpers =====================

__device__ __forceinline__ uint32_t smem_u32(const void* p) {
    uint32_t a;
    asm("{ .reg .u64 t; cvta.to.shared.u64 t, %1; cvt.u32.u64 %0, t; }"
        : "=r"(a) : "l"(p));
    return a;
}

#define MBARRIER_INIT(addr, cnt) \
    asm volatile("mbarrier.init.shared.b64 [%0], %1;" :: "r"((uint32_t)(addr)), "r"((uint32_t)(cnt)) : "memory")

#define MBARRIER_EXPECT_TX(addr, bytes) \
    asm volatile("mbarrier.arrive.expect_tx.shared.b64 _, [%0], %1;" :: "r"((uint32_t)(addr)), "r"((uint32_t)(bytes)) : "memory")

#define MBARRIER_ARRIVE(addr) \
    asm volatile("mbarrier.arrive.release.cta.shared::cta.b64 _, [%0];" :: "r"((uint32_t)(addr)) : "memory")

#define MBARRIER_WAIT_PARITY_ACQ(mbar_smem_addr, phase_parity) do { \
    uint32_t _mbar = (uint32_t)(mbar_smem_addr); \
    uint32_t _parity = (uint32_t)(phase_parity); \
    uint32_t _done; \
    asm volatile( \
        "{\n\t" \
        ".reg .pred p;\n\t" \
        "mbarrier.try_wait.parity.acquire.cta.shared::cta.b64 p, [%1], %2;\n\t" \
        "selp.b32 %0, 1, 0, p;\n\t" \
        "}" \
        : "=r"(_done) : "r"(_mbar), "r"(_parity) : "memory"); \
    if (!_done) { \
        asm volatile( \
            "{\n\t" \
            ".reg .pred P1;\n\t" \
            "WAIT_LOOP_%=:\n\t" \
            "mbarrier.try_wait.parity.acquire.cta.shared::cta.b64 P1, [%0], %1, 0x989680;\n\t" \
            "@P1 bra.uni WAIT_DONE_%=;\n\t" \
            "bra.uni WAIT_LOOP_%=;\n\t" \
            "WAIT_DONE_%=:\n\t" \
            "}" \
            :: "r"(_mbar), "r"(_parity) : "memory"); \
    } \
} while (0)

#define MBARRIER_WAIT_PARITY_RELAXED(mbar_smem_addr, phase_parity) do { \
    uint32_t _mbar = (uint32_t)(mbar_smem_addr); \
    uint32_t _parity = (uint32_t)(phase_parity); \
    uint32_t _done; \
    asm volatile( \
        "{\n\t" \
        ".reg .pred p;\n\t" \
        "mbarrier.try_wait.parity.relaxed.cta.shared::cta.b64 p, [%1], %2, 0x989680;\n\t" \
        "selp.b32 %0, 1, 0, p;\n\t" \
        "}" \
        : "=r"(_done) : "r"(_mbar), "r"(_parity) : "memory"); \
    if (!_done) { \
        asm volatile( \
            "{\n\t" \
            ".reg .pred P1;\n\t" \
            "WAIT_LOOP_%=:\n\t" \
            "mbarrier.try_wait.parity.relaxed.cta.shared::cta.b64 P1, [%0], %1, 0x989680;\n\t" \
            "@P1 bra.uni WAIT_DONE_%=;\n\t" \
            "bra.uni WAIT_LOOP_%=;\n\t" \
            "WAIT_DONE_%=:\n\t" \
            "}" \
            :: "r"(_mbar), "r"(_parity) : "memory"); \
    } \
} while (0)

#define FENCE_PROXY_ASYNC_SHARED_CTA() \
    asm volatile("fence.proxy.async.shared::cta;" ::: "memory")

#define LDSM_X4(r0, r1, r2, r3, addr) \
    asm volatile("ldmatrix.sync.aligned.m8n8.x4.shared.b16 {%0,%1,%2,%3}, [%4];" \
                 : "=r"(r0), "=r"(r1), "=r"(r2), "=r"(r3) : "r"(addr))

__device__ __forceinline__ void tma2d(uint32_t dst, const CUtensorMap* tm,
                                      int cx, int cy, uint32_t mbar) {
    asm volatile(
        "cp.async.bulk.tensor.2d.shared::cta.global.tile.mbarrier::complete_tx::bytes "
        "[%0], [%1, {%2, %3}], [%4];"
        :: "r"(dst), "l"(tm), "r"(cx), "r"(cy), "r"(mbar) : "memory");
}

__device__ __forceinline__ void mma_f16_16x8x16(
    float& c0, float& c1, float& c2, float& c3,
    uint32_t a0, uint32_t a1, uint32_t a2, uint32_t a3,
    uint32_t b0, uint32_t b1) {
    asm volatile(
        "mma.sync.aligned.m16n8k16.row.col.f32.f16.f16.f32 "
        "{%0,%1,%2,%3}, {%4,%5,%6,%7}, {%8,%9}, {%0,%1,%2,%3};"
        : "+f"(c0), "+f"(c1), "+f"(c2), "+f"(c3)
        : "r"(a0), "r"(a1), "r"(a2), "r"(a3), "r"(b0), "r"(b1));
}

// ===================== Kernel 1: fused prep (dequant W + convert x) ==============
static constexpr int DEQ_BLOCKS = GROUPS / 256;              // 2048
static constexpr int CVT_BLOCKS = (M_TOT * K_TOT / 8) / 256; // 8192

__global__ void prep_kernel(const int* __restrict__ q3,
                            const float* __restrict__ norm,
                            __half* __restrict__ W,
                            const float4* __restrict__ x,
                            uint4* __restrict__ xo) {
    if (blockIdx.x < DEQ_BLOCKS) {
        int g = blockIdx.x * 256 + threadIdx.x;
        const float mv = norm[g];
        const float sc = mv * (2.0f / 7.0f);
        const int4* p4 = reinterpret_cast<const int4*>(q3 + (size_t)g * 12);
        int4 pa = p4[0], pb = p4[1], pc = p4[2];
        int b[12] = {pa.x, pa.y, pa.z, pa.w, pb.x, pb.y, pb.z, pb.w, pc.x, pc.y, pc.z, pc.w};
        __half2 w[16];
#pragma unroll
        for (int t = 0; t < 4; t++) {
            int b0 = b[t * 3], b1 = b[t * 3 + 1], b2 = b[t * 3 + 2];
            int v[8];
            v[0] = b0 & 7;
            v[1] = (b0 >> 3) & 7;
            v[2] = ((b0 >> 6) & 3) | ((b1 & 1) << 2);
            v[3] = (b1 >> 1) & 7;
            v[4] = (b1 >> 4) & 7;
            v[5] = ((b1 >> 7) & 1) | ((b2 & 3) << 1);
            v[6] = (b2 >> 2) & 7;
            v[7] = (b2 >> 5) & 7;
#pragma unroll
            for (int j = 0; j < 4; j++) {
                float f0 = fmaf((float)v[2 * j],     sc, -mv);
                float f1 = fmaf((float)v[2 * j + 1], sc, -mv);
                w[t * 4 + j] = __floats2half2_rn(f0, f1);
            }
        }
        uint4* dst = reinterpret_cast<uint4*>(W + (size_t)g * 32);
        const uint32_t* wu = reinterpret_cast<const uint32_t*>(w);
#pragma unroll
        for (int q = 0; q < 4; q++)
            dst[q] = make_uint4(wu[q * 4], wu[q * 4 + 1], wu[q * 4 + 2], wu[q * 4 + 3]);
    } else {
        int i = (blockIdx.x - DEQ_BLOCKS) * 256 + threadIdx.x;
        float4 v0 = x[2 * i];
        float4 v1 = x[2 * i + 1];
        __half2 h0 = __floats2half2_rn(v0.x, v0.y);
        __half2 h1 = __floats2half2_rn(v0.z, v0.w);
        __half2 h2 = __floats2half2_rn(v1.x, v1.y);
        __half2 h3 = __floats2half2_rn(v1.z, v1.w);
        xo[i] = make_uint4(*reinterpret_cast<uint32_t*>(&h0), *reinterpret_cast<uint32_t*>(&h1),
                           *reinterpret_cast<uint32_t*>(&h2), *reinterpret_cast<uint32_t*>(&h3));
    }
}

// ===================== Kernel 2: persistent mma.sync fp16 GEMM =====================
// 288 threads: warps 0..7 compute 64x32 warp tiles, warp 8 = TMA producer.
// Grid 296 persistent CTAs; all tiles uniform 128x128 full-K; pipeline state
// (stage index s, phase ph) carried across tile boundaries on both sides.

__global__ void __launch_bounds__(288, 2)
gemm_f16_kernel(const float* __restrict__ bias, float* __restrict__ out,
                const __grid_constant__ CUtensorMap tmA,
                const __grid_constant__ CUtensorMap tmB) {
    extern __shared__ char smem[];
    const uint32_t sb = smem_u32(smem);
    const int tid = threadIdx.x;
    const int wid = tid >> 5;
    const int lid = tid & 31;

    if (tid == 0) {
        for (int s = 0; s < STAGES; s++) {
            MBARRIER_INIT(sb + SM_FULL + s * 8, 1);
            MBARRIER_INIT(sb + SM_EMPTY + s * 8, 8);
        }
        FENCE_PROXY_ASYNC_SHARED_CTA();
    }
    __syncthreads();

    if (wid == 8) {
        // ---------------- TMA producer warp (persistent, no drain) ----------------
        if (lid == 0) {
            int s = 0, ph = 1;
            for (int u = blockIdx.x; u < NTILES; u += GRID) {
                const int m0 = (u & 31) * BM;
                const int n0 = (u >> 5) * BN;
                for (int j = 0; j < NCH; j++) {
                    MBARRIER_WAIT_PARITY_RELAXED(sb + SM_EMPTY + s * 8, ph);
                    MBARRIER_EXPECT_TX(sb + SM_FULL + s * 8, STAGE_BYTES);
                    uint32_t dstA = sb + SM_TILE + s * STAGE_BYTES;
                    tma2d(dstA, &tmA, j * BK, m0, sb + SM_FULL + s * 8);
                    tma2d(dstA + A_STAGE_BYTES, &tmB, j * BK, n0, sb + SM_FULL + s * 8);
                    if (++s == STAGES) { s = 0; ph ^= 1; }
                }
            }
        }
        return;
    }

    // ---------------- compute warps ----------------
    const int warp_m = wid & 1;       // 64 rows
    const int warp_n = wid >> 1;      // 32 cols
    const int lr4 = lid >> 2;
    const int lc4 = lid & 3;
    const int mi = lid >> 3;
    const int r  = lid & 7;

    uint32_t aRow[4];
#pragma unroll
    for (int m = 0; m < 4; m++)
        aRow[m] = (uint32_t)(warp_m * 64 + m * 16 + (mi & 1) * 8 + r) * 128u;
    uint32_t cA[4];
#pragma unroll
    for (int k = 0; k < 4; k++)
        cA[k] = 16u * (uint32_t)((2 * k + (mi >> 1)) ^ r);

    uint32_t bRow[2];
#pragma unroll
    for (int t = 0; t < 2; t++)
        bRow[t] = (uint32_t)(warp_n * 32 + t * 16 + (mi >> 1) * 8 + r) * 128u;
    uint32_t cB[4];
#pragma unroll
    for (int k = 0; k < 4; k++)
        cB[k] = 16u * (uint32_t)((2 * k + (mi & 1)) ^ r);

    int s = 0, ph = 0;
    for (int u = blockIdx.x; u < NTILES; u += GRID) {
        const int m0 = (u & 31) * BM;
        const int n0 = (u >> 5) * BN;

        float acc[4][4][4];
#pragma unroll
        for (int m = 0; m < 4; m++)
#pragma unroll
            for (int n = 0; n < 4; n++)
#pragma unroll
                for (int q = 0; q < 4; q++) acc[m][n][q] = 0.0f;

        for (int j = 0; j < NCH; j++) {
            MBARRIER_WAIT_PARITY_ACQ(sb + SM_FULL + s * 8, ph);
            const uint32_t pa = sb + SM_TILE + s * STAGE_BYTES;
            const uint32_t pb = pa + A_STAGE_BYTES;

#pragma unroll
            for (int k = 0; k < 4; k++) {
                uint32_t af[4][4];
#pragma unroll
                for (int m = 0; m < 4; m++)
                    LDSM_X4(af[m][0], af[m][1], af[m][2], af[m][3], pa + aRow[m] + cA[k]);
                uint32_t bf[4][2];
#pragma unroll
                for (int t = 0; t < 2; t++)
                    LDSM_X4(bf[2 * t][0], bf[2 * t][1], bf[2 * t + 1][0], bf[2 * t + 1][1],
                            pb + bRow[t] + cB[k]);
#pragma unroll
                for (int m = 0; m < 4; m++)
#pragma unroll
                    for (int n = 0; n < 4; n++)
                        mma_f16_16x8x16(acc[m][n][0], acc[m][n][1], acc[m][n][2], acc[m][n][3],
                                        af[m][0], af[m][1], af[m][2], af[m][3],
                                        bf[n][0], bf[n][1]);
            }
            // SAFE release: the k=3 HMMAs above scoreboard-waited on every
            // LDSM result, so when this arrive issues (in-order), all of this
            // warp's smem reads for the stage have completed.
            if (lid == 0) MBARRIER_ARRIVE(sb + SM_EMPTY + s * 8);
            if (++s == STAGES) { s = 0; ph ^= 1; }
        }

        // ---------------- epilogue (overlapped with producer prefetch) --------
        const int orow0 = m0 + warp_m * 64 + lr4;
        const int ocol0 = n0 + warp_n * 32 + 2 * lc4;
#pragma unroll
        for (int m = 0; m < 4; m++) {
#pragma unroll
            for (int n = 0; n < 4; n++) {
                const int col = ocol0 + n * 8;
                const float2 bv = *reinterpret_cast<const float2*>(bias + col);
                float* p0 = out + (size_t)(orow0 + m * 16) * N_TOT + col;
                float* p1 = out + (size_t)(orow0 + m * 16 + 8) * N_TOT + col;
                *reinterpret_cast<float2*>(p0) =
                    make_float2(acc[m][n][0] + bv.x, acc[m][n][1] + bv.y);
                *reinterpret_cast<float2*>(p1) =
                    make_float2(acc[m][n][2] + bv.x, acc[m][n][3] + bv.y);
            }
        }
    }
}

// ===================== Host =====================

typedef CUresult (*cuTensorMapEncodeTiled_t)(
    CUtensorMap*, CUtensorMapDataType, cuuint32_t, void*,
    const cuuint64_t*, const cuuint64_t*, const cuuint32_t*, const cuuint32_t*,
    CUtensorMapInterleave, CUtensorMapSwizzle, CUtensorMapL2promotion,
    CUtensorMapFloatOOBfill);

static void make_desc(cuTensorMapEncodeTiled_t enc, CUtensorMap* tm,
                      const void* base, uint32_t box_rows) {
    cuuint64_t dims[2] = {(cuuint64_t)K_TOT, (cuuint64_t)4096};
    cuuint64_t strides[1] = {(cuuint64_t)K_TOT * sizeof(__half)};
    cuuint32_t box[2] = {(cuuint32_t)BK, box_rows};
    cuuint32_t estr[2] = {1, 1};
    enc(tm, CU_TENSOR_MAP_DATA_TYPE_UINT16, 2, const_cast<void*>(base),
        dims, strides, box, estr,
        CU_TENSOR_MAP_INTERLEAVE_NONE, CU_TENSOR_MAP_SWIZZLE_128B,
        CU_TENSOR_MAP_L2_PROMOTION_L2_128B, CU_TENSOR_MAP_FLOAT_OOB_FILL_NONE);
}

extern "C" void kernel_launch(void* const* d_in, const int* in_sizes, int n_in,
                              void* d_out, int out_size) {
    const float* x    = (const float*)d_in[0];
    const int*   q3   = (const int*)d_in[1];
    const float* norm = (const float*)d_in[2];
    const float* bias = (const float*)d_in[3];
    float* out = (float*)d_out;

    void* wptr = nullptr;
    cudaGetSymbolAddress(&wptr, g_W);
    void* xptr = nullptr;
    cudaGetSymbolAddress(&xptr, g_X);

    void* fn = nullptr;
    cudaDriverEntryPointQueryResult qr;
    cudaGetDriverEntryPointByVersion("cuTensorMapEncodeTiled", &fn, 12000,
                                     cudaEnableDefault, &qr);
    cuTensorMapEncodeTiled_t enc = (cuTensorMapEncodeTiled_t)fn;

    CUtensorMap tmA, tmB;
    make_desc(enc, &tmA, xptr, (uint32_t)BM);
    make_desc(enc, &tmB, wptr, (uint32_t)BN);

    prep_kernel<<<DEQ_BLOCKS + CVT_BLOCKS, 256>>>(
        q3, norm, (__half*)wptr, (const float4*)x, (uint4*)xptr);

    cudaFuncSetAttribute(gemm_f16_kernel,
                         cudaFuncAttributeMaxDynamicSharedMemorySize, SMEM_TOTAL);
    gemm_f16_kernel<<<GRID, 288, SMEM_TOTAL>>>(bias, out, tmA, tmB);
}